// round 17
// baseline (speedup 1.0000x reference)
#include <cuda_runtime.h>
#include <cuda_fp16.h>
#include <math.h>
#include <stdint.h>

// Problem dims (fixed per setup_inputs)
#define B_   4
#define T_   4096
#define K_   1024          // Din == D == 1024
#define D_   1024
#define M_   (B_*T_)       // 16384

// ---------------- scratch (device globals; no allocations allowed) ---------
__device__ float  g_buf0[(size_t)M_ * D_];   // 64 MB (reused as half)
__device__ float  g_buf1[(size_t)M_ * D_];   // 64 MB (reused as half)
__device__ float  g_buf2[(size_t)M_ * D_];   // 64 MB (reused as half)
__device__ __half g_wTh[(size_t)5 * K_ * D_]; // 10 MB transposed fp16 weights
__device__ int    g_cnt[1024];                // dependency counters

// counter layout
#define CNT_G   0      // [0..127]   gates per row-block (to 16)
#define CNT_P1  128    // [128..131] scan p1 per batch (to 64)
#define CNT_P2  132    // [132..135] scan p2 per batch (to 16)
#define CNT_P3  136    // [136..263] scan p3 per row-block (to 2)
#define CNT_S0  264    // [264..391] chain bias per row-block (to 8)
#define CNT_S1  392    // [392..519] chain gelu per row-block (to 8)
#define CNT_S2  520    // [520..647] chain resid per row-block (to 8)

#define CHUNK 32
#define NC    (T_/CHUNK)    // 128
__device__ float g_cA[B_*NC*D_];
__device__ float g_cP[B_*NC*D_];
__device__ float g_cC[B_*NC*D_];

// ---------------- helpers ----------------------------------------------------
__device__ __forceinline__ uint32_t smem_u32(const void* p) {
    uint32_t a;
    asm("{ .reg .u64 t; cvta.to.shared.u64 t, %1; cvt.u32.u64 %0, t; }" : "=r"(a) : "l"(p));
    return a;
}
__device__ __forceinline__ void cp_async16(uint32_t saddr, const void* gptr) {
    asm volatile("cp.async.cg.shared.global [%0], [%1], 16;" :: "r"(saddr), "l"(gptr));
}
#define CP_COMMIT() asm volatile("cp.async.commit_group;" ::: "memory")
#define CP_WAIT1()  asm volatile("cp.async.wait_group 1;"  ::: "memory")
#define CP_WAIT0()  asm volatile("cp.async.wait_group 0;"  ::: "memory")

#define LDSM_X4(r0, r1, r2, r3, addr) \
    asm volatile("ldmatrix.sync.aligned.m8n8.x4.shared.b16 {%0,%1,%2,%3}, [%4];" \
                 : "=r"(r0), "=r"(r1), "=r"(r2), "=r"(r3) : "r"(addr))

__device__ __forceinline__ void mma_f16(float c[4], const uint32_t a[4],
                                        uint32_t b0, uint32_t b1) {
    asm volatile(
        "mma.sync.aligned.m16n8k16.row.col.f32.f16.f16.f32 "
        "{%0,%1,%2,%3}, {%4,%5,%6,%7}, {%8,%9}, {%0,%1,%2,%3};"
        : "+f"(c[0]), "+f"(c[1]), "+f"(c[2]), "+f"(c[3])
        : "r"(a[0]), "r"(a[1]), "r"(a[2]), "r"(a[3]), "r"(b0), "r"(b1));
}

__device__ __forceinline__ int ld_acquire(const int* p) {
    int v;
    asm volatile("ld.acquire.gpu.global.s32 %0, [%1];" : "=r"(v) : "l"(p) : "memory");
    return v;
}
__device__ __forceinline__ void wait_cnt(int slot, int target, int tid) {
    if (tid == 0) {
        const int* c = &g_cnt[slot];
        while (ld_acquire(c) < target) __nanosleep(64);
    }
    __syncthreads();
}
__device__ __forceinline__ void signal_cnt(int slot, int tid) {
    __threadfence();
    __syncthreads();
    if (tid == 0) atomicAdd(&g_cnt[slot], 1);
}

// ---------------- fp16 mma.sync GEMM core (round-12 verified, BK=64) ----------
#define BMm 128
#define BNm 128
#define BKm 64
#define STEPSm (K_/BKm)        // 16
#define STAGE_B 16384
#define NSTG 3
#define GEMM_SMEM (2*NSTG*STAGE_B)   // 98304 B

struct Frag { float acc[4][4][4]; };

__device__ __forceinline__ void gemm_mainloop(
    const __half* __restrict__ Ab, const __half* __restrict__ Bb,
    uint32_t sbase, int tid, int lane, int wm, int wn, Frag& fr)
{
    const uint32_t aB = sbase;
    const uint32_t bB = sbase + NSTG * STAGE_B;

    const int r0 = tid >> 3;
    const int g8 = (tid & 7) * 8;
    const uint32_t soff0 = ((uint32_t)r0 << 7)
                         + ((((uint32_t)tid & 7) << 4) ^ (((uint32_t)r0 & 7) << 4));

    const int rr = lane & 7;
    const uint32_t swz   = (uint32_t)rr << 4;
    const uint32_t akoff = (uint32_t)((lane >> 4) & 1) << 4;
    const uint32_t bkoff = (uint32_t)((lane >> 3) & 1) << 4;
    const int a_row8 = (lane >> 3) & 1;
    const int b_n8   = (lane >> 4) & 1;
    uint32_t aoff[4];
#pragma unroll
    for (int mi = 0; mi < 4; mi++)
        aoff[mi] = (uint32_t)(wm * 64 + mi * 16 + a_row8 * 8 + rr) << 7;
    uint32_t boff[2];
#pragma unroll
    for (int j = 0; j < 2; j++)
        boff[j] = (uint32_t)(wn * 32 + j * 16 + b_n8 * 8 + rr) << 7;

#pragma unroll
    for (int mi = 0; mi < 4; mi++)
#pragma unroll
        for (int ni = 0; ni < 4; ni++)
#pragma unroll
            for (int q = 0; q < 4; q++) fr.acc[mi][ni][q] = 0.f;

    uint32_t af[2][4][4];
    uint32_t bq[2][2][4];

#define ISSUE_STAGE(S) do {                                                     \
        const int _k0 = (S) * BKm;                                              \
        const uint32_t _sa = aB + ((S) % NSTG) * STAGE_B + soff0;               \
        const uint32_t _sb = bB + ((S) % NSTG) * STAGE_B + soff0;               \
        _Pragma("unroll")                                                       \
        for (int j = 0; j < 4; j++) {                                           \
            const size_t go = (size_t)(r0 + 32 * j) * K_ + _k0 + g8;            \
            const uint32_t so = (uint32_t)(32 * j) << 7;                        \
            cp_async16(_sa + so, Ab + go);                                      \
            cp_async16(_sb + so, Bb + go);                                      \
        }                                                                       \
    } while (0)

#define LOAD_FRAGS(SLOT, SA, SB, KO) do {                                       \
        const uint32_t _ax = ((KO) + akoff) ^ swz;                              \
        const uint32_t _bx = ((KO) + bkoff) ^ swz;                              \
        _Pragma("unroll")                                                       \
        for (int mi = 0; mi < 4; mi++)                                          \
            LDSM_X4(af[SLOT][mi][0], af[SLOT][mi][1],                           \
                    af[SLOT][mi][2], af[SLOT][mi][3], (SA) + aoff[mi] + _ax);   \
        _Pragma("unroll")                                                       \
        for (int j = 0; j < 2; j++)                                             \
            LDSM_X4(bq[SLOT][j][0], bq[SLOT][j][1],                             \
                    bq[SLOT][j][2], bq[SLOT][j][3], (SB) + boff[j] + _bx);      \
    } while (0)

    ISSUE_STAGE(0); CP_COMMIT();
    ISSUE_STAGE(1); CP_COMMIT();
    CP_WAIT1();
    __syncthreads();

    uint32_t sa = aB, sb = bB;
    LOAD_FRAGS(0, sa, sb, 0u);

    for (int s = 0; s < STEPSm; s++) {
#pragma unroll
        for (int ks = 0; ks < 4; ks++) {
            if (ks < 3) {
                LOAD_FRAGS((ks + 1) & 1, sa, sb, (uint32_t)(ks + 1) * 32);
            } else if (s + 1 < STEPSm) {
                if (s + 2 < STEPSm) { ISSUE_STAGE(s + 2); CP_COMMIT(); CP_WAIT1(); }
                else                { CP_WAIT0(); }
                __syncthreads();
                sa = aB + ((s + 1) % NSTG) * STAGE_B;
                sb = bB + ((s + 1) % NSTG) * STAGE_B;
                LOAD_FRAGS(0, sa, sb, 0u);
            }
            const int p = ks & 1;
#pragma unroll
            for (int mi = 0; mi < 4; mi++)
#pragma unroll
                for (int ni = 0; ni < 4; ni++)
                    mma_f16(fr.acc[mi][ni], af[p][mi],
                            bq[p][ni >> 1][(ni & 1) * 2],
                            bq[p][ni >> 1][(ni & 1) * 2 + 1]);
        }
    }
#undef ISSUE_STAGE
#undef LOAD_FRAGS
}

__device__ __forceinline__ void h8_to_f(const uint4 u, float* f) {
    const __half2* p = reinterpret_cast<const __half2*>(&u);
#pragma unroll
    for (int i = 0; i < 4; i++) {
        float2 t = __half22float2(p[i]);
        f[i * 2] = t.x; f[i * 2 + 1] = t.y;
    }
}

// ================= MEGA KERNEL: gates -> scan -> chain -> LN ==================
// bid ranges: [0,2048) gates | [2048,2304) p1 | [2304,2368) p2 | [2368,2624) p3
//             [2624,3648) s0 | [3648,4672) s1 | [4672,5696) s2 | [5696,6720) LN
#define NBLK 6720

__global__ __launch_bounds__(256, 2)
void mega(const __half* __restrict__ xh, const float* __restrict__ bin_,
          const float* __restrict__ rnn_start,
          const float* __restrict__ hidden, float* __restrict__ hidden_out,
          const float* __restrict__ bout, const float* __restrict__ b1,
          const float* __restrict__ b2,
          __half* __restrict__ vh, __half* __restrict__ fh,
          __half* __restrict__ hsh, __half* __restrict__ oh,
          __half* __restrict__ x_h, __half* __restrict__ zh,
          const float* __restrict__ ln_g, const float* __restrict__ ln_b,
          float* __restrict__ out)
{
    extern __shared__ float smf[];
    const int bid = blockIdx.x;
    const int tid = threadIdx.x, lane = tid & 31, wid = tid >> 5;
    const int wm = wid >> 2, wn = wid & 3;

    if (bid < 2048 || (bid >= 2624 && bid < 5696)) {
        // ================= GEMM roles =================
        const uint32_t sbase = smem_u32(smf);
        int bm, bn, z = 0, stage;
        const __half* A; const __half* Bt; const float* bias;
        if (bid < 2048) {
            stage = -1;
            bm = bid >> 4; bn = (bid >> 1) & 7; z = bid & 1;
            A = xh; Bt = g_wTh + (size_t)z * K_ * D_; bias = bin_ + z * D_;
        } else {
            const int q = bid - 2624;
            stage = q >> 10;                 // 0,1,2
            const int t = q & 1023;
            bm = t >> 3; bn = t & 7;
            if (stage == 0)      { A = hsh; Bt = g_wTh + 2 * (size_t)K_ * D_; bias = bout; }
            else if (stage == 1) { A = oh;  Bt = g_wTh + 3 * (size_t)K_ * D_; bias = b1;   }
            else                 { A = x_h; Bt = g_wTh + 4 * (size_t)K_ * D_; bias = b2;   }
        }

        if (stage == 0)      wait_cnt(CNT_P3 + bm, 2, tid);
        else if (stage == 1) wait_cnt(CNT_S0 + bm, 8, tid);
        else if (stage == 2) wait_cnt(CNT_S1 + bm, 8, tid);

        Frag fr;
        gemm_mainloop(A + (size_t)bm * BMm * K_, Bt + (size_t)bn * BNm * K_,
                      sbase, tid, lane, wm, wn, fr);

        __half* C;
        if (stage == -1) C = z ? fh : vh;
        else             C = (stage == 0) ? oh : (stage == 1) ? x_h : zh;

        const int r_base = bm * BMm + wm * 64 + (lane >> 2);
        const int c_base = bn * BNm + wn * 32 + ((lane & 3) << 1);
#pragma unroll
        for (int mi = 0; mi < 4; mi++) {
            const int gr0 = r_base + mi * 16;
            const int gr1 = gr0 + 8;
            float rs0 = 0.f, rs1 = 0.f;
            if (stage == -1 && z) { rs0 = rnn_start[gr0]; rs1 = rnn_start[gr1]; }
#pragma unroll
            for (int ni = 0; ni < 4; ni++) {
                const int gc = c_base + ni * 8;
                float bb0 = bias[gc], bb1 = bias[gc + 1];
                float v0 = fr.acc[mi][ni][0] + bb0;
                float v1 = fr.acc[mi][ni][1] + bb1;
                float v2 = fr.acc[mi][ni][2] + bb0;
                float v3 = fr.acc[mi][ni][3] + bb1;
                if (stage == -1) {
                    if (z == 0) {
                        v0 = tanhf(v0); v1 = tanhf(v1); v2 = tanhf(v2); v3 = tanhf(v3);
                    } else {
                        v0 = (1.f - rs0) / (1.f + expf(-v0));
                        v1 = (1.f - rs0) / (1.f + expf(-v1));
                        v2 = (1.f - rs1) / (1.f + expf(-v2));
                        v3 = (1.f - rs1) / (1.f + expf(-v3));
                    }
                } else if (stage == 1) {
                    v0 = 0.5f * v0 * (1.f + erff(v0 * 0.70710678118654752f));
                    v1 = 0.5f * v1 * (1.f + erff(v1 * 0.70710678118654752f));
                    v2 = 0.5f * v2 * (1.f + erff(v2 * 0.70710678118654752f));
                    v3 = 0.5f * v3 * (1.f + erff(v3 * 0.70710678118654752f));
                } else if (stage == 2) {
                    float2 e0 = __half22float2(*reinterpret_cast<const __half2*>(oh + (size_t)gr0 * D_ + gc));
                    float2 e1 = __half22float2(*reinterpret_cast<const __half2*>(oh + (size_t)gr1 * D_ + gc));
                    v0 += e0.x; v1 += e0.y; v2 += e1.x; v3 += e1.y;
                }
                *reinterpret_cast<__half2*>(C + (size_t)gr0 * D_ + gc) = __floats2half2_rn(v0, v1);
                *reinterpret_cast<__half2*>(C + (size_t)gr1 * D_ + gc) = __floats2half2_rn(v2, v3);
            }
        }

        if (stage == -1)     signal_cnt(CNT_G + bm, tid);
        else if (stage == 0) signal_cnt(CNT_S0 + bm, tid);
        else if (stage == 1) signal_cnt(CNT_S1 + bm, tid);
        else                 signal_cnt(CNT_S2 + bm, tid);

    } else if (bid < 2304) {
        // ================= scan pass 1 =================
        const int i = bid - 2048;            // 0..255
        wait_cnt(CNT_G + (i >> 1), 16, tid);
        const int idx = i * 256 + tid;
        const int d8 = idx & 127;
        const int gi = idx >> 7;             // global chunk 0..511
        const int b  = gi >> 7;
        size_t base = (size_t)gi * CHUNK * (D_ / 8) + d8;
        float A[8], h[8];
#pragma unroll
        for (int q = 0; q < 8; q++) { A[q] = 1.f; h[q] = 0.f; }
#pragma unroll 4
        for (int t = 0; t < CHUNK; t++) {
            float f[8], v[8];
            h8_to_f(reinterpret_cast<const uint4*>(fh)[base + (size_t)t * (D_ / 8)], f);
            h8_to_f(reinterpret_cast<const uint4*>(vh)[base + (size_t)t * (D_ / 8)], v);
#pragma unroll
            for (int q = 0; q < 8; q++) {
                A[q] *= f[q];
                h[q] = f[q] * h[q] + (1.f - f[q]) * v[q];
            }
        }
        float4* pA = reinterpret_cast<float4*>(g_cA) + idx * 2;
        float4* pP = reinterpret_cast<float4*>(g_cP) + idx * 2;
        pA[0] = make_float4(A[0], A[1], A[2], A[3]);
        pA[1] = make_float4(A[4], A[5], A[6], A[7]);
        pP[0] = make_float4(h[0], h[1], h[2], h[3]);
        pP[1] = make_float4(h[4], h[5], h[6], h[7]);
        signal_cnt(CNT_P1 + b, tid);

    } else if (bid < 2368) {
        // ================= scan pass 2 (d-width 64, 64KB smem) =================
        const int k  = bid - 2304;           // 0..63
        const int b  = k >> 4;
        const int d0 = (k & 15) * 64;
        wait_cnt(CNT_P1 + b, 64, tid);
        float* sA = smf;                     // [128][64]
        float* sP = smf + NC * 64;
#pragma unroll 4
        for (int j = 0; j < 32; j++) {
            int i2 = tid + 256 * j;          // 8192 elems
            int c = i2 >> 6, dd = i2 & 63;
            size_t g = ((size_t)b * NC + c) * D_ + d0 + dd;
            sA[i2] = g_cA[g];
            sP[i2] = g_cP[g];
        }
        __syncthreads();
        if (tid < 64) {
            const int dd = tid;
            float h = hidden[(size_t)b * D_ + d0 + dd];
            for (int c = 0; c < NC; c++) {
                g_cC[((size_t)b * NC + c) * D_ + d0 + dd] = h;
                h = sA[c * 64 + dd] * h + sP[c * 64 + dd];
            }
            hidden_out[(size_t)b * D_ + d0 + dd] = h;
        }
        signal_cnt(CNT_P2 + b, tid);

    } else if (bid < 2624) {
        // ================= scan pass 3 =================
        const int i = bid - 2368;            // 0..255
        const int b = i >> 6;
        wait_cnt(CNT_P2 + b, 16, tid);
        const int idx = i * 256 + tid;
        const int d8 = idx & 127;
        const int gi = idx >> 7;
        size_t base = (size_t)gi * CHUNK * (D_ / 8) + d8;
        const float4* pC = reinterpret_cast<const float4*>(g_cC) + idx * 2;
        float4 c0 = pC[0], c1 = pC[1];
        float h[8] = { c0.x, c0.y, c0.z, c0.w, c1.x, c1.y, c1.z, c1.w };
#pragma unroll 4
        for (int t = 0; t < CHUNK; t++) {
            float f[8], v[8];
            h8_to_f(reinterpret_cast<const uint4*>(fh)[base + (size_t)t * (D_ / 8)], f);
            h8_to_f(reinterpret_cast<const uint4*>(vh)[base + (size_t)t * (D_ / 8)], v);
            uint4 o;
            __half2* po = reinterpret_cast<__half2*>(&o);
#pragma unroll
            for (int q = 0; q < 8; q++)
                h[q] = f[q] * h[q] + (1.f - f[q]) * v[q];
#pragma unroll
            for (int q = 0; q < 4; q++)
                po[q] = __floats2half2_rn(h[q * 2], h[q * 2 + 1]);
            reinterpret_cast<uint4*>(hsh)[base + (size_t)t * (D_ / 8)] = o;
        }
        signal_cnt(CNT_P3 + (i >> 1), tid);

    } else {
        // ================= LayerNorm: 16 rows per CTA =================
        const int q = bid - 5696;            // 0..1023
        wait_cnt(CNT_S2 + (q >> 3), 8, tid);
        __shared__ float sh_s[8], sh_ss[8];
        const int w = tid >> 5, l = tid & 31;
        for (int r = 0; r < 16; r++) {
            const int row = q * 16 + r;
            const __half2* zp = reinterpret_cast<const __half2*>(zh + (size_t)row * D_) + tid * 2;
            float2 p0 = __half22float2(zp[0]);
            float2 p1 = __half22float2(zp[1]);
            float x0 = p0.x, x1 = p0.y, x2 = p1.x, x3 = p1.y;
            float s  = x0 + x1 + x2 + x3;
            float ss = x0 * x0 + x1 * x1 + x2 * x2 + x3 * x3;
#pragma unroll
            for (int o = 16; o > 0; o >>= 1) {
                s  += __shfl_xor_sync(0xFFFFFFFFu, s, o);
                ss += __shfl_xor_sync(0xFFFFFFFFu, ss, o);
            }
            if (l == 0) { sh_s[w] = s; sh_ss[w] = ss; }
            __syncthreads();
            if (w == 0) {
                s  = (l < 8) ? sh_s[l]  : 0.f;
                ss = (l < 8) ? sh_ss[l] : 0.f;
#pragma unroll
                for (int o = 4; o > 0; o >>= 1) {
                    s  += __shfl_xor_sync(0xFFFFFFFFu, s, o);
                    ss += __shfl_xor_sync(0xFFFFFFFFu, ss, o);
                }
                if (l == 0) { sh_s[0] = s; sh_ss[0] = ss; }
            }
            __syncthreads();
            float mean = sh_s[0] * (1.f / D_);
            float var  = sh_ss[0] * (1.f / D_) - mean * mean;
            float rstd = rsqrtf(var + 1e-5f);
            float4 gg = reinterpret_cast<const float4*>(ln_g)[tid];
            float4 bb = reinterpret_cast<const float4*>(ln_b)[tid];
            float4 y;
            y.x = (x0 - mean) * rstd * gg.x + bb.x;
            y.y = (x1 - mean) * rstd * gg.y + bb.y;
            y.z = (x2 - mean) * rstd * gg.z + bb.z;
            y.w = (x3 - mean) * rstd * gg.w + bb.w;
            reinterpret_cast<float4*>(out + (size_t)row * D_)[tid] = y;
            __syncthreads();
        }
    }
}

// ---------------- x -> fp16 copy + counter reset ------------------------------
__global__ void cvt_x_h(const float4* __restrict__ x, __half2* __restrict__ xh)
{
    if (blockIdx.x == 0) {
#pragma unroll
        for (int j = 0; j < 4; j++) g_cnt[threadIdx.x + 256 * j] = 0;
    }
    int i = blockIdx.x * blockDim.x + threadIdx.x;
    float4 v = x[i];
    xh[i * 2 + 0] = __floats2half2_rn(v.x, v.y);
    xh[i * 2 + 1] = __floats2half2_rn(v.z, v.w);
}

// ---------------- weight transpose + fp16 -------------------------------------
__global__ void transpose_h(const float* __restrict__ s0, const float* __restrict__ s1,
                            const float* __restrict__ s2, const float* __restrict__ s3,
                            const float* __restrict__ s4, __half* __restrict__ dst)
{
    __shared__ float tile[32][33];
    const int z = blockIdx.z;
    const float* src = (z == 0) ? s0 : (z == 1) ? s1 : (z == 2) ? s2 : (z == 3) ? s3 : s4;
    __half* d = dst + (size_t)z * K_ * D_;
    const int n0 = blockIdx.x * 32, k0 = blockIdx.y * 32;
    const int tx = threadIdx.x, ty = threadIdx.y;
#pragma unroll
    for (int r = 0; r < 32; r += 8)
        tile[ty + r][tx] = src[(size_t)(k0 + ty + r) * D_ + n0 + tx];
    __syncthreads();
#pragma unroll
    for (int r = 0; r < 32; r += 8)
        d[(size_t)(n0 + ty + r) * K_ + k0 + tx] = __float2half_rn(tile[tx][ty + r]);
}

// ---------------- launch -------------------------------------------------------
extern "C" void kernel_launch(void* const* d_in, const int* in_sizes, int n_in,
                              void* d_out, int out_size)
{
    const float* x         = (const float*)d_in[0];
    const float* hidden    = (const float*)d_in[1];
    const float* rnn_start = (const float*)d_in[2];
    const float* Win       = (const float*)d_in[3];
    const float* bin_      = (const float*)d_in[4];
    const float* Wout      = (const float*)d_in[5];
    const float* bout      = (const float*)d_in[6];
    const float* W1        = (const float*)d_in[7];
    const float* b1        = (const float*)d_in[8];
    const float* W2        = (const float*)d_in[9];
    const float* b2        = (const float*)d_in[10];
    const float* ln_g      = (const float*)d_in[11];
    const float* ln_b      = (const float*)d_in[12];

    float* out        = (float*)d_out;
    float* hidden_out = out + (size_t)M_ * D_;

    float *buf0, *buf1, *buf2;
    __half* wTh;
    cudaGetSymbolAddress((void**)&buf0, g_buf0);
    cudaGetSymbolAddress((void**)&buf1, g_buf1);
    cudaGetSymbolAddress((void**)&buf2, g_buf2);
    cudaGetSymbolAddress((void**)&wTh,  g_wTh);

    cudaFuncSetAttribute(mega, cudaFuncAttributeMaxDynamicSharedMemorySize, GEMM_SMEM);

    __half* xh  = (__half*)buf2;   // fp16 x (first 32MB of buf2)
    __half* vh  = (__half*)buf0;
    __half* fh  = (__half*)buf1;
    __half* hsh = (__half*)buf2;   // overwrites xh rows only after all gate readers done
    __half* oh  = (__half*)buf1;   // after p3 (last fh reader) of row-block done
    __half* x_h = (__half*)buf0;   // after s0 (last vh... p3) done
    __half* zh  = (__half*)((float*)buf2 + (size_t)M_ * D_ / 2);   // 2nd half of buf2

    transpose_h<<<dim3(32, 32, 5), dim3(32, 8)>>>(
        Win, Win + (size_t)K_ * D_, Wout, W1, W2, wTh);
    cvt_x_h<<<(M_ * K_) / (256 * 4), 256>>>((const float4*)x, (__half2*)xh);

    mega<<<NBLK, 256, GEMM_SMEM>>>(xh, bin_, rnn_start, hidden, hidden_out,
                                   bout, b1, b2, vh, fh, hsh, oh, x_h, zh,
                                   ln_g, ln_b, out);
}